// round 11
// baseline (speedup 1.0000x reference)
#include <cuda_runtime.h>
#include <cuda_bf16.h>
#include <cstdint>
#include <cfloat>

// ---------------- problem constants ----------------
#define TEMP        0.1f
#define LN2F        0.6931471805599453f
#define LOG2EF      1.4426950408889634f
#define N_TOTAL     65536
#define D_DIM       512
#define P_DIM       128
#define NUM_CTAS    148
#define THREADS     384
#define WARPS       12
#define ROWS_PER_WARP 16
#define NUM_CHUNKS  (N_TOTAL / ROWS_PER_WARP)   // 4096
#define WSTRIDE     (NUM_CTAS * WARPS)          // 1776
#define KSTEPS      (D_DIM / 16)                // 32
#define NFRAGS      (P_DIM / 8)                 // 16

// SMEM layout (bytes, dynamic)
#define SM_W     0                         // 128 f32 weights
#define SM_RED   512                       // 12 f32 block-reduce
#define SM_BF    1024                      // B frag pairs: 256 * 32 * 16B = 131072
#define SMEM_TOTAL (SM_BF + 131072)        // 132096

__device__ float        g_partials[NUM_CTAS];
__device__ unsigned int g_done = 0;

// mma.sync m16n8k16 bf16 -> f32 (sm_80+ feature set; compiles on compute_103)
__device__ __forceinline__ void mma16816(float* c, const uint32_t* a,
                                         uint32_t b0, uint32_t b1) {
    asm volatile(
        "mma.sync.aligned.m16n8k16.row.col.f32.bf16.bf16.f32 "
        "{%0,%1,%2,%3}, {%4,%5,%6,%7}, {%8,%9}, {%0,%1,%2,%3};"
        : "+f"(c[0]), "+f"(c[1]), "+f"(c[2]), "+f"(c[3])
        : "r"(a[0]), "r"(a[1]), "r"(a[2]), "r"(a[3]), "r"(b0), "r"(b1));
}

__device__ __forceinline__ uint32_t pack_bf16(float x, float y) {
    __nv_bfloat162 h = __floats2bfloat162_rn(x, y);
    return *(uint32_t*)&h;
}

__device__ __forceinline__ float ex2(float x) {
    float y;
    asm("ex2.approx.ftz.f32 %0, %1;" : "=f"(y) : "f"(x));
    return y;
}

// Load one m16k16 A fragment (4 regs) from global, fp32 -> bf16, and
// accumulate sum-of-squares for the two rows this lane touches.
__device__ __forceinline__ void load_afrag(uint32_t* a, const float* p, float* ss) {
    float2 x0 = *(const float2*)p;                    // (r,   k0)
    float2 x1 = *(const float2*)(p + 8 * D_DIM);      // (r+8, k0)
    float2 x2 = *(const float2*)(p + 8);              // (r,   k0+8)
    float2 x3 = *(const float2*)(p + 8 * D_DIM + 8);  // (r+8, k0+8)
    ss[0] += x0.x*x0.x + x0.y*x0.y + x2.x*x2.x + x2.y*x2.y;
    ss[1] += x1.x*x1.x + x1.y*x1.y + x3.x*x3.x + x3.y*x3.y;
    a[0] = pack_bf16(x0.x, x0.y);
    a[1] = pack_bf16(x1.x, x1.y);
    a[2] = pack_bf16(x2.x, x2.y);
    a[3] = pack_bf16(x3.x, x3.y);
}

// ---------------- main kernel ----------------
extern "C" __global__ void __launch_bounds__(THREADS, 1)
mrc_loss_main(const float* __restrict__ backbone,     // (N, D)
              const float* __restrict__ proto,        // (P, D)
              const int*   __restrict__ labels,       // (N, P)
              const float* __restrict__ weights,      // (P,)
              float*       __restrict__ out)
{
    extern __shared__ char smem[];
    float* w_s   = (float*)(smem + SM_W);
    float* red_s = (float*)(smem + SM_RED);
    char*  bfrag = smem + SM_BF;

    const int tid  = threadIdx.x;
    const int lane = tid & 31;
    const int wid  = tid >> 5;    // 0..11
    const int lq   = lane >> 2;   // lane/4  (0..7)
    const int lr   = lane & 3;    // lane%4

    if (tid < P_DIM) w_s[tid] = weights[tid];

    // ---- stage B (prototypes) once, as paired mma B-fragments ----
    // pair idx = ks*8 + nfp (nfp = nf/2). Per lane (16B):
    //   {nf.b0, nf.b1, (nf+1).b0, (nf+1).b1},
    //   nf.bX: n = nf*8 + lq, k0 = ks*16 + lr*2 (+8 for b1)
    for (int idx = wid; idx < KSTEPS * (NFRAGS / 2); idx += WARPS) {
        int ks  = idx >> 3, nfp = idx & 7;
        int n0  = nfp * 16 + lq;           // nf = 2*nfp
        int k0  = ks * 16 + lr * 2;
        const float* pr0 = proto + (size_t)n0 * D_DIM + k0;
        const float* pr1 = pr0 + 8 * D_DIM;     // n0 + 8
        float2 a0 = *(const float2*)pr0;
        float2 a1 = *(const float2*)(pr0 + 8);
        float2 b0 = *(const float2*)pr1;
        float2 b1 = *(const float2*)(pr1 + 8);
        uint4 w;
        w.x = pack_bf16(a0.x, a0.y);
        w.y = pack_bf16(a1.x, a1.y);
        w.z = pack_bf16(b0.x, b0.y);
        w.w = pack_bf16(b1.x, b1.y);
        *(uint4*)(bfrag + ((size_t)idx * 32 + lane) * 16) = w;
    }
    __syncthreads();
    // After this point warps free-run: no intra-loop barriers (B read-only,
    // all per-chunk state lives in registers).

    float local_sum = 0.0f;

    for (int wt = blockIdx.x * WARPS + wid; wt < NUM_CHUNKS; wt += WSTRIDE) {
        const int rowbase = wt * ROWS_PER_WARP;   // warp owns 16 rows
        const float* a0p = backbone + (size_t)(rowbase + lq) * D_DIM + lr * 2;

        float c[NFRAGS][4];
        #pragma unroll
        for (int nf = 0; nf < NFRAGS; nf++)
            #pragma unroll
            for (int e = 0; e < 4; e++) c[nf][e] = 0.0f;

        float ss[2] = {0.f, 0.f};             // sumsq rows lq / lq+8
        uint32_t a[3][4];                      // prefetch ring, distance 2

        load_afrag(a[0], a0p,      ss);        // ks = 0
        load_afrag(a[1], a0p + 16, ss);        // ks = 1

        #pragma unroll
        for (int ks = 0; ks < KSTEPS; ks++) {
            if (ks < KSTEPS - 2)               // prefetch ks+2
                load_afrag(a[(ks + 2) % 3], a0p + (ks + 2) * 16, ss);
            const uint4* brow = (const uint4*)bfrag
                              + (size_t)ks * (NFRAGS / 2) * 32 + lane;
            const uint32_t* ac = a[ks % 3];
            #pragma unroll
            for (int nfp = 0; nfp < NFRAGS / 2; nfp++) {
                uint4 b = brow[nfp * 32];      // one LDS.128 feeds 2 mma
                mma16816(c[2 * nfp],     ac, b.x, b.y);
                mma16816(c[2 * nfp + 1], ac, b.z, b.w);
            }
        }

        // ---- quad-reduce row sum-squares (all lanes get the row value) ----
        #pragma unroll
        for (int h = 0; h < 2; h++) {
            float v = ss[h];
            v += __shfl_xor_sync(0xFFFFFFFFu, v, 1);
            v += __shfl_xor_sync(0xFFFFFFFFu, v, 2);
            ss[h] = v;
        }

        // ---- register epilogue: masked log-softmax per row, quad-parallel --
        // Row h: r = rowbase + h*8 + lq. Its 128 logits live in the quad's 4
        // lanes: lane lr holds cols {nf*8+lr*2, +1}, nf=0..15.
        // Work in log2 domain: t = logit*log2e; exp(l)=ex2(t);
        // ln-result recovered via *LN2 at the end. Max-subtraction omitted:
        // cancels exactly in sml - sm*log(se), logits bounded (~60).
        #pragma unroll
        for (int h = 0; h < 2; h++) {
            const int r = rowbase + h * 8 + lq;
            const float inv2 =
                LOG2EF / (fmaxf(sqrtf(ss[h]), 1e-12f) * TEMP);
            const int2* lab = (const int2*)(labels + (size_t)r * P_DIM) + lr;

            float se = 0.0f, sml = 0.0f, sm = 0.0f;
            #pragma unroll
            for (int nf = 0; nf < NFRAGS; nf++) {
                int2 lb = __ldg(&lab[nf * 4]);
                float2 wv = *(const float2*)&w_s[nf * 8 + lr * 2];
                float t0 = c[nf][2 * h + 0] * inv2;
                float t1 = c[nf][2 * h + 1] * inv2;
                float mk0 = (float)lb.x * wv.x;
                float mk1 = (float)lb.y * wv.y;
                se  += ex2(t0) * (1.0f - mk0) + ex2(t1) * (1.0f - mk1);
                sml += mk0 * t0 + mk1 * t1;
                sm  += mk0 + mk1;
            }
            se  += __shfl_xor_sync(0xFFFFFFFFu, se, 1);
            se  += __shfl_xor_sync(0xFFFFFFFFu, se, 2);
            sml += __shfl_xor_sync(0xFFFFFFFFu, sml, 1);
            sml += __shfl_xor_sync(0xFFFFFFFFu, sml, 2);
            sm  += __shfl_xor_sync(0xFFFFFFFFu, sm, 1);
            sm  += __shfl_xor_sync(0xFFFFFFFFu, sm, 2);
            if (lr == 0)
                local_sum += -(TEMP * LN2F) * (sml - sm * __log2f(se));
        }
    }

    // ---- deterministic block reduction ----
    #pragma unroll
    for (int off = 16; off > 0; off >>= 1)
        local_sum += __shfl_down_sync(0xFFFFFFFFu, local_sum, off);
    if ((tid & 31) == 0) red_s[wid] = local_sum;
    __syncthreads();
    if (tid == 0) {
        float s = 0.0f;
        #pragma unroll
        for (int w = 0; w < WARPS; w++) s += red_s[w];
        g_partials[blockIdx.x] = s;
        __threadfence();
        unsigned int prev = atomicAdd(&g_done, 1u);
        if (prev == NUM_CTAS - 1) {            // last CTA: fixed-order final sum
            float tot = 0.0f;
            #pragma unroll 4
            for (int i = 0; i < NUM_CTAS; i++) tot += g_partials[i];
            out[0] = tot / (float)N_TOTAL;     // LAMBDA_PROTOTYPE = 1
            g_done = 0;                        // re-arm for next graph replay
        }
    }
}

// ---------------- launch ----------------
extern "C" void kernel_launch(void* const* d_in, const int* in_sizes, int n_in,
                              void* d_out, int out_size) {
    // metadata order: outputs(0), targets(1), backbone_features(2),
    //                 prototype_features(3), prototype_labels(4), prototype_weights(5)
    const float* backbone = (const float*)d_in[2];
    const float* proto    = (const float*)d_in[3];
    const int*   labels   = (const int*)d_in[4];
    const float* weights  = (const float*)d_in[5];
    float* out = (float*)d_out;

    static bool attr_set = false;
    if (!attr_set) {
        cudaFuncSetAttribute(mrc_loss_main,
                             cudaFuncAttributeMaxDynamicSharedMemorySize, SMEM_TOTAL);
        attr_set = true;
    }

    mrc_loss_main<<<NUM_CTAS, THREADS, SMEM_TOTAL>>>(backbone, proto, labels,
                                                     weights, out);
}